// round 10
// baseline (speedup 1.0000x reference)
#include <cuda_runtime.h>
#include <cuda_fp16.h>
#include <cstdint>

// Problem constants
static constexpr int B_ = 32, T_ = 200, K_ = 50, D_ = 100;
static constexpr int NTILES = B_ * T_;   // 6400
static constexpr int THREADS = 512;      // 16 warps: 2 independent halves of 8

// fp16 weight strides (halfs); fp32 staging strides (floats).
// Bank classes: 216,120 halfs (B-frags) verified CF; 200,104 floats mod 32 = 8 -> CF for LDS.64 phases.
static constexpr int SWH = 216;   // Wht  [112 x 216]
static constexpr int SWR = 120;   // Wrel [112 x 120]
static constexpr int SXF = 200;   // X   [50 x 200] fp32 (no pad cols; last kstep peeled)
static constexpr int SRF = 104;   // REL [50 x 104] fp32 (cols 100..103 zero pad)

static constexpr int XF_TILE = 50 * SXF * 4;   // 40000
static constexpr int RF_TILE = 50 * SRF * 4;   // 20800

static constexpr int OFF_WHT  = 0;                  // 48384
static constexpr int OFF_WREL = 48384;              // 26880 -> 75264
static constexpr int OFF_XF   = 75264;              // 2*40000 -> 155264
static constexpr int OFF_RELF = 155264;             // 2*20800 -> 196864
static constexpr int OFF_BHT  = 196864;             // 448
static constexpr int OFF_BREL = 197312;             // 448 -> 197760
static constexpr int OFF_EP   = 197760;             // 2*128 fl -> 198784
static constexpr int OFF_IDS  = 198784;             // 2 halves * 2 bufs * 152 ints -> 201216
static constexpr int SMEM_BYTES = 201216;
static constexpr int ZERO_BYTES = OFF_BHT;          // weights + staging pads must be 0

__device__ __forceinline__ void mma16816(float& c0, float& c1, float& c2, float& c3,
                                         uint32_t a0, uint32_t a1, uint32_t a2, uint32_t a3,
                                         uint32_t b0, uint32_t b1) {
    asm volatile("mma.sync.aligned.m16n8k16.row.col.f32.f16.f16.f32 "
                 "{%0,%1,%2,%3}, {%4,%5,%6,%7}, {%8,%9}, {%0,%1,%2,%3};"
                 : "+f"(c0), "+f"(c1), "+f"(c2), "+f"(c3)
                 : "r"(a0), "r"(a1), "r"(a2), "r"(a3), "r"(b0), "r"(b1));
}
__device__ __forceinline__ uint32_t f2h2(float a, float b) {
    __half2 h = __floats2half2_rn(a, b);
    return *reinterpret_cast<uint32_t*>(&h);
}
__device__ __forceinline__ float tanh_approx(float x) {
    float y;
    asm("tanh.approx.f32 %0, %1;" : "=f"(y) : "f"(x));
    return y;
}
__device__ __forceinline__ uint32_t smem_u32(const void* p) {
    uint32_t a;
    asm("{ .reg .u64 t; cvta.to.shared.u64 t, %1; cvt.u32.u64 %0, t; }" : "=r"(a) : "l"(p));
    return a;
}
__device__ __forceinline__ void cp_async16(uint32_t dst, const void* src) {
    asm volatile("cp.async.cg.shared.global [%0], [%1], 16;" :: "r"(dst), "l"(src) : "memory");
}
#define CP_COMMIT() asm volatile("cp.async.commit_group;" ::: "memory")
#define CP_WAIT0()  asm volatile("cp.async.wait_group 0;" ::: "memory")
#define CP_WAIT1()  asm volatile("cp.async.wait_group 1;" ::: "memory")
#define BARH(s)     asm volatile("bar.sync %0, 256;" :: "r"((s) + 1) : "memory")

extern __shared__ __align__(16) unsigned char smem_raw[];

__global__ __launch_bounds__(THREADS, 1)
void outer_encoder_mma(const unsigned int* __restrict__ idsw,
                       const float* __restrict__ emb,
                       const float* __restrict__ Wht,
                       const float* __restrict__ bht,
                       const float* __restrict__ Wrel,
                       const float* __restrict__ brel,
                       float* __restrict__ out) {
    unsigned char* sm = smem_raw;
    const uint32_t sb = smem_u32(sm);
    const int tid = threadIdx.x, w = tid >> 5, lane = tid & 31;
    const int s = tid >> 8;               // half-slot (0/1)
    const int ht = tid & 255;             // thread-in-half
    const int wh = w & 7;                 // warp-in-half
    const int gid = lane >> 2, tig = lane & 3;

    float* sbht = (float*)(sm + OFF_BHT);
    float* sbrl = (float*)(sm + OFF_BREL);
    float* sEp  = (float*)(sm + OFF_EP)  + s * 128;
    int*   sIds = (int*)  (sm + OFF_IDS) + s * 304;   // two buffers of 152
    float* sXf  = (float*)(sm + OFF_XF   + s * XF_TILE);
    float* sRf  = (float*)(sm + OFF_RELF + s * RF_TILE);

    // ---- zero weights + staging (pads must be 0 and stay 0) ----
    for (int i = tid; i < ZERO_BYTES / 16; i += THREADS)
        ((uint4*)sm)[i] = make_uint4(0, 0, 0, 0);
    __syncthreads();

    // ---- weights -> fp16 smem ----
    {
        const float4* g = (const float4*)Wht;              // [100][200] -> 5000 f4
        for (int i = tid; i < 5000; i += THREADS) {
            int d = i / 50, c4 = i % 50;
            float4 v = __ldg(&g[i]);
            uint2 hv; hv.x = f2h2(v.x, v.y); hv.y = f2h2(v.z, v.w);
            *(uint2*)(sm + OFF_WHT + (d * SWH + c4 * 4) * 2) = hv;
        }
        const float4* gr = (const float4*)Wrel;            // [100][100] -> 2500 f4
        for (int i = tid; i < 2500; i += THREADS) {
            int d = i / 25, c4 = i % 25;
            float4 v = __ldg(&gr[i]);
            uint2 hv; hv.x = f2h2(v.x, v.y); hv.y = f2h2(v.z, v.w);
            *(uint2*)(sm + OFF_WREL + (d * SWR + c4 * 4) * 2) = hv;
        }
        if (tid < 112) {
            sbht[tid] = (tid < D_) ? bht[tid]  : 0.f;
            sbrl[tid] = (tid < D_) ? brel[tid] : 0.f;
        }
    }
    const int is64 = ((idsw[1] | idsw[3] | idsw[5] | idsw[7]) == 0) ? 1 : 0;
    __syncthreads();   // after this the two halves decouple

    const int mt = w & 3, nh = (w >> 2) & 1;
    const int arow = mt * 16 + gid;
    const int row0 = (arow     < K_) ? arow     : (K_ - 1);
    const int row1 = (arow + 8 < K_) ? arow + 8 : (K_ - 1);
    const bool skipA1 = (mt == 3);        // rows 56..63 all clamp & discard
    const int NTHIS = (nh == 0) ? 7 : 6;  // nh=1 covers cols 56..103 (104..111 were pure pad)
    const __half* pWH = (const __half*)(sm + OFF_WHT);
    const __half* pWR = (const __half*)(sm + OFF_WREL);
    const uint32_t dXb = sb + OFF_XF   + s * XF_TILE + lane * 16;
    const uint32_t dRb = sb + OFF_RELF + s * RF_TILE + lane * 16;

    const int hs = blockIdx.x * 2 + s;
    const int NH = gridDim.x * 2;

    // wsum role (constant per thread)
    const int wpart = (ht < 100) ? 0 : 2;
    const int wcol  = (ht < 100) ? ht : ((ht < 200) ? ht - 100 : 0);

    // ---- prologue: ids + gather for the first tile (two separate commit groups) ----
    if (ht < 150) {
        const long long e = (long long)hs * 150 + ht;
        sIds[ht] = (int)(is64 ? idsw[2 * e] : idsw[e]);
    }
    BARH(s);
    if (lane < 25) {
        for (int task = wh; task < 50; task += 8) {
            const int id = sIds[task * 3 + 1];
            cp_async16(dRb + task * SRF * 4,
                       (const char*)emb + (long long)id * 400 + lane * 16);
        }
    }
    CP_COMMIT();   // group: REL
    if (lane < 25) {
        for (int task = wh; task < 100; task += 8) {
            const int k = task >> 1, h = task & 1;
            const int id = sIds[k * 3 + (h ? 2 : 0)];
            cp_async16(dXb + (k * SXF + h * 100) * 4,
                       (const char*)emb + (long long)id * 400 + lane * 16);
        }
    }
    CP_COMMIT();   // group: X

    int pp = 0;
    for (int tile = hs; tile < NTILES; tile += NH) {
        const bool has_next = (tile + NH) < NTILES;
        int* curIds = sIds + pp * 152;
        int* nxtIds = sIds + (pp ^ 1) * 152;

        CP_WAIT1();   // REL landed (X may still be in flight)
        BARH(s);      // all warps' REL visible; prev-iter smem reads ordered

        // next-tile ids: LDG now, STS before mid barrier (latency hidden under GEMM2)
        int rid = 0;
        const bool pre = has_next && (ht < 150);
        if (pre) {
            const long long e = (long long)(tile + NH) * 150 + ht;
            rid = (int)(is64 ? idsw[2 * e] : idsw[e]);
        }

        float acc1[7][4], acc2[7][4];
#pragma unroll
        for (int nt = 0; nt < 7; nt++)
#pragma unroll
            for (int j = 0; j < 4; j++) { acc1[nt][j] = 0.f; acc2[nt][j] = 0.f; }

        {   // GEMM2: D2 = REL[64x104] @ Wrel^T   (6 full ksteps + peeled ks=6)
            const float* pA0 = sRf + row0 * SRF;
            const float* pA1 = sRf + row1 * SRF;
#pragma unroll
            for (int ks = 0; ks < 6; ks++) {
                const int k0 = ks * 16 + tig * 2;
                float2 f0 = *(const float2*)(pA0 + k0);
                float2 f2 = *(const float2*)(pA0 + k0 + 8);
                float2 f1 = skipA1 ? f0 : *(const float2*)(pA1 + k0);
                float2 f3 = skipA1 ? f2 : *(const float2*)(pA1 + k0 + 8);
                uint32_t a0 = f2h2(f0.x, f0.y), a1 = f2h2(f1.x, f1.y);
                uint32_t a2 = f2h2(f2.x, f2.y), a3 = f2h2(f3.x, f3.y);
#pragma unroll
                for (int nt = 0; nt < 7; nt++) {
                    if (nt < 6 || nh == 0) {
                        const int brow = nh * 56 + nt * 8 + gid;
                        uint32_t b0 = *(const uint32_t*)(pWR + brow * SWR + k0);
                        uint32_t b1 = *(const uint32_t*)(pWR + brow * SWR + k0 + 8);
                        mma16816(acc2[nt][0], acc2[nt][1], acc2[nt][2], acc2[nt][3],
                                 a0, a1, a2, a3, b0, b1);
                    }
                }
            }
            {   // ks = 6: k0 in [96..102] (cols 100..103 are zero pad); k0+8 out of data -> a2=a3=b1=0
                const int k0 = 96 + tig * 2;
                float2 f0 = *(const float2*)(pA0 + k0);
                float2 f1 = skipA1 ? f0 : *(const float2*)(pA1 + k0);
                uint32_t a0 = f2h2(f0.x, f0.y), a1 = f2h2(f1.x, f1.y);
#pragma unroll
                for (int nt = 0; nt < 7; nt++) {
                    if (nt < 6 || nh == 0) {
                        const int brow = nh * 56 + nt * 8 + gid;
                        uint32_t b0 = *(const uint32_t*)(pWR + brow * SWR + k0);
                        mma16816(acc2[nt][0], acc2[nt][1], acc2[nt][2], acc2[nt][3],
                                 a0, a1, 0u, 0u, b0, 0u);
                    }
                }
            }
        }
        if (pre) nxtIds[ht] = rid;
        CP_WAIT0();   // X landed
        BARH(s);      // all warps: GEMM2 done with sRf; X + ids visible

        // overlap: next tile's REL gather streams in under GEMM1 + epilogue
        if (lane < 25 && has_next) {
            for (int task = wh; task < 50; task += 8) {
                const int id = nxtIds[task * 3 + 1];
                cp_async16(dRb + task * SRF * 4,
                           (const char*)emb + (long long)id * 400 + lane * 16);
            }
        }
        CP_COMMIT();   // group: REL

        {   // GEMM1: D1 = X[64x200] @ Wht^T   (12 full ksteps + peeled ks=12)
            const float* pA0 = sXf + row0 * SXF;
            const float* pA1 = sXf + row1 * SXF;
#pragma unroll
            for (int ks = 0; ks < 12; ks++) {
                const int k0 = ks * 16 + tig * 2;
                float2 f0 = *(const float2*)(pA0 + k0);
                float2 f2 = *(const float2*)(pA0 + k0 + 8);
                float2 f1 = skipA1 ? f0 : *(const float2*)(pA1 + k0);
                float2 f3 = skipA1 ? f2 : *(const float2*)(pA1 + k0 + 8);
                uint32_t a0 = f2h2(f0.x, f0.y), a1 = f2h2(f1.x, f1.y);
                uint32_t a2 = f2h2(f2.x, f2.y), a3 = f2h2(f3.x, f3.y);
#pragma unroll
                for (int nt = 0; nt < 7; nt++) {
                    if (nt < 6 || nh == 0) {
                        const int brow = nh * 56 + nt * 8 + gid;
                        uint32_t b0 = *(const uint32_t*)(pWH + brow * SWH + k0);
                        uint32_t b1 = *(const uint32_t*)(pWH + brow * SWH + k0 + 8);
                        mma16816(acc1[nt][0], acc1[nt][1], acc1[nt][2], acc1[nt][3],
                                 a0, a1, a2, a3, b0, b1);
                    }
                }
            }
            {   // ks = 12: k0 in [192..198] real data; k0+8 beyond 200 -> a2=a3=b1=0
                const int k0 = 192 + tig * 2;
                float2 f0 = *(const float2*)(pA0 + k0);
                float2 f1 = skipA1 ? f0 : *(const float2*)(pA1 + k0);
                uint32_t a0 = f2h2(f0.x, f0.y), a1 = f2h2(f1.x, f1.y);
#pragma unroll
                for (int nt = 0; nt < 7; nt++) {
                    if (nt < 6 || nh == 0) {
                        const int brow = nh * 56 + nt * 8 + gid;
                        uint32_t b0 = *(const uint32_t*)(pWH + brow * SWH + k0);
                        mma16816(acc1[nt][0], acc1[nt][1], acc1[nt][2], acc1[nt][3],
                                 a0, a1, 0u, 0u, b0, 0u);
                    }
                }
            }
        }

        // ---- fused epilogue: e partials (nh=1 skips nt=6; its cols were pure pad) ----
        {
            float e0 = 0.f, e1 = 0.f;
#pragma unroll
            for (int nt = 0; nt < 7; nt++) {
                if (nt < 6 || nh == 0) {
                    const int c0 = nh * 56 + nt * 8 + tig * 2;
                    const float bh0 = sbht[c0], bh1 = sbht[c0 + 1];
                    const float br0 = sbrl[c0], br1 = sbrl[c0 + 1];
                    e0 += tanh_approx(acc1[nt][0] + bh0) * (acc2[nt][0] + br0)
                        + tanh_approx(acc1[nt][1] + bh1) * (acc2[nt][1] + br1);
                    e1 += tanh_approx(acc1[nt][2] + bh0) * (acc2[nt][2] + br0)
                        + tanh_approx(acc1[nt][3] + bh1) * (acc2[nt][3] + br1);
                }
            }
            e0 += __shfl_xor_sync(0xffffffffu, e0, 1);
            e0 += __shfl_xor_sync(0xffffffffu, e0, 2);
            e1 += __shfl_xor_sync(0xffffffffu, e1, 1);
            e1 += __shfl_xor_sync(0xffffffffu, e1, 2);
            if (tig == 0) {
                sEp[nh * 64 + arow]     = e0;
                sEp[nh * 64 + arow + 8] = e1;
            }
        }
        BARH(s);   // sXf free for overwrite; sEp ready

        // overlap: next tile's X gather streams in under softmax + wsum
        if (lane < 25 && has_next) {
            for (int task = wh; task < 100; task += 8) {
                const int k = task >> 1, h = task & 1;
                const int id = nxtIds[k * 3 + (h ? 2 : 0)];
                cp_async16(dXb + (k * SXF + h * 100) * 4,
                           (const char*)emb + (long long)id * 400 + lane * 16);
            }
        }
        CP_COMMIT();   // group: X

        // ---- wsum loads batch 1 (MLP=25) issued BEFORE softmax to hide L2 latency ----
        const float* ebase = emb + wcol;
        float v1[25];
        const bool dow = (wh < 7);
        if (dow) {
#pragma unroll
            for (int j = 0; j < 25; j++) {
                const int id = curIds[j * 3 + wpart];
                v1[j] = __ldg(ebase + (long long)id * D_);
            }
        }

        // ---- softmax (redundant per-warp, registers only) ----
        float al0, al1;
        {
            float v0 = (lane < K_) ? (sEp[lane] + sEp[64 + lane]) : -1e30f;
            float vv1 = (lane + 32 < K_) ? (sEp[lane + 32] + sEp[64 + lane + 32]) : -1e30f;
            float m = fmaxf(v0, vv1);
#pragma unroll
            for (int off = 16; off > 0; off >>= 1)
                m = fmaxf(m, __shfl_xor_sync(0xffffffffu, m, off));
            float x0 = (lane < K_) ? __expf(v0 - m) : 0.f;
            float x1 = (lane + 32 < K_) ? __expf(vv1 - m) : 0.f;
            float su = x0 + x1;
#pragma unroll
            for (int off = 16; off > 0; off >>= 1)
                su += __shfl_xor_sync(0xffffffffu, su, off);
            const float inv = __fdividef(1.f, su);
            al0 = x0 * inv;        // alpha[lane]
            al1 = x1 * inv;        // alpha[lane+32]
        }

        // ---- wsum: issue batch 2, consume batch 1, consume batch 2 ----
        if (dow) {
            float v2[25];
#pragma unroll
            for (int j = 0; j < 25; j++) {
                const int id = curIds[(25 + j) * 3 + wpart];
                v2[j] = __ldg(ebase + (long long)id * D_);
            }
            float acc = 0.f;
#pragma unroll
            for (int j = 0; j < 25; j++) {
                const float al = __shfl_sync(0xffffffffu, al0, j);
                acc += al * v1[j];
            }
#pragma unroll
            for (int j = 0; j < 25; j++) {
                const int k = 25 + j;
                const float al = (k < 32) ? __shfl_sync(0xffffffffu, al0, k)
                                          : __shfl_sync(0xffffffffu, al1, k - 32);
                acc += al * v2[j];
            }
            if (ht < 200) out[(long long)tile * 200 + ht] = acc;
        }
        // no trailing barrier: next iteration's head BARH orders
        // sEp reads vs next epilogue writes and curIds reads vs next id stores.
        pp ^= 1;
    }
}

extern "C" void kernel_launch(void* const* d_in, const int* in_sizes, int n_in,
                              void* d_out, int out_size) {
    const unsigned int* ids = nullptr;
    const float *emb = nullptr, *Wht = nullptr, *Wrel = nullptr;
    const float *bht = nullptr, *brel = nullptr;

    for (int i = 0; i < n_in; i++) {
        const int sz = in_sizes[i];
        if      (sz == B_ * T_ * K_ * 3) ids  = (const unsigned int*)d_in[i];
        else if (sz == 500000 * D_)      emb  = (const float*)d_in[i];
        else if (sz == D_ * 2 * D_)      Wht  = (const float*)d_in[i];
        else if (sz == D_ * D_)          Wrel = (const float*)d_in[i];
        else if (sz == D_) {
            if (!bht) bht = (const float*)d_in[i];
            else      brel = (const float*)d_in[i];
        }
    }

    int dev = 0;
    cudaGetDevice(&dev);
    int sms = 148;
    cudaDeviceGetAttribute(&sms, cudaDevAttrMultiProcessorCount, dev);
    if (sms <= 0) sms = 148;

    cudaFuncSetAttribute(outer_encoder_mma,
                         cudaFuncAttributeMaxDynamicSharedMemorySize, SMEM_BYTES);
    outer_encoder_mma<<<sms, THREADS, SMEM_BYTES>>>(
        ids, emb, Wht, bht, Wrel, brel, (float*)d_out);
}

// round 11
// speedup vs baseline: 1.0316x; 1.0316x over previous
#include <cuda_runtime.h>
#include <cuda_fp16.h>
#include <cstdint>

// Problem constants
static constexpr int B_ = 32, T_ = 200, K_ = 50, D_ = 100;
static constexpr int NTILES = B_ * T_;   // 6400
static constexpr int THREADS = 512;      // 16 warps: 2 independent halves of 8

// fp16 weight strides (halfs); fp32 staging strides (floats). Bank patterns verified CF.
static constexpr int SWH = 216;   // Wht  [112 x 216]
static constexpr int SWR = 120;   // Wrel [112 x 120]
static constexpr int SXF = 216;   // X   [50 x 216] fp32 (cols 200..215 zero)
static constexpr int SRF = 120;   // REL [50 x 120] fp32 (cols 100..119 zero)

static constexpr int XF_TILE = 50 * SXF * 4;   // 43200
static constexpr int RF_TILE = 50 * SRF * 4;   // 24000

static constexpr int OFF_WHT  = 0;                  // 48384
static constexpr int OFF_WREL = 48384;              // 26880 -> 75264
static constexpr int OFF_XF   = 75264;              // 2*43200 -> 161664
static constexpr int OFF_RELF = 161664;             // 2*24000 -> 209664
static constexpr int OFF_BHT  = 209664;             // 448
static constexpr int OFF_BREL = 210112;             // 448 -> 210560
static constexpr int OFF_EP   = 210560;             // 2*128 fl -> 211584
static constexpr int OFF_IDS  = 211584;             // 2 halves * 2 bufs * 152 ints -> 214016
static constexpr int SMEM_BYTES = 214016;
static constexpr int ZERO_BYTES = OFF_BHT;          // weights + staging pads must be 0

__device__ __forceinline__ void mma16816(float& c0, float& c1, float& c2, float& c3,
                                         uint32_t a0, uint32_t a1, uint32_t a2, uint32_t a3,
                                         uint32_t b0, uint32_t b1) {
    asm volatile("mma.sync.aligned.m16n8k16.row.col.f32.f16.f16.f32 "
                 "{%0,%1,%2,%3}, {%4,%5,%6,%7}, {%8,%9}, {%0,%1,%2,%3};"
                 : "+f"(c0), "+f"(c1), "+f"(c2), "+f"(c3)
                 : "r"(a0), "r"(a1), "r"(a2), "r"(a3), "r"(b0), "r"(b1));
}
__device__ __forceinline__ uint32_t f2h2(float a, float b) {
    __half2 h = __floats2half2_rn(a, b);
    return *reinterpret_cast<uint32_t*>(&h);
}
__device__ __forceinline__ float tanh_approx(float x) {
    float y;
    asm("tanh.approx.f32 %0, %1;" : "=f"(y) : "f"(x));
    return y;
}
__device__ __forceinline__ uint32_t smem_u32(const void* p) {
    uint32_t a;
    asm("{ .reg .u64 t; cvta.to.shared.u64 t, %1; cvt.u32.u64 %0, t; }" : "=r"(a) : "l"(p));
    return a;
}
__device__ __forceinline__ void cp_async16(uint32_t dst, const void* src) {
    asm volatile("cp.async.cg.shared.global [%0], [%1], 16;" :: "r"(dst), "l"(src) : "memory");
}
#define CP_COMMIT() asm volatile("cp.async.commit_group;" ::: "memory")
#define CP_WAIT0()  asm volatile("cp.async.wait_group 0;" ::: "memory")
#define CP_WAIT1()  asm volatile("cp.async.wait_group 1;" ::: "memory")
#define BARH(s)     asm volatile("bar.sync %0, 256;" :: "r"((s) + 1) : "memory")

extern __shared__ __align__(16) unsigned char smem_raw[];

__global__ __launch_bounds__(THREADS, 1)
void outer_encoder_mma(const unsigned int* __restrict__ idsw,
                       const float* __restrict__ emb,
                       const float* __restrict__ Wht,
                       const float* __restrict__ bht,
                       const float* __restrict__ Wrel,
                       const float* __restrict__ brel,
                       float* __restrict__ out) {
    unsigned char* sm = smem_raw;
    const uint32_t sb = smem_u32(sm);
    const int tid = threadIdx.x, w = tid >> 5, lane = tid & 31;
    const int s = tid >> 8;               // half-slot (0/1)
    const int ht = tid & 255;             // thread-in-half
    const int wh = w & 7;                 // warp-in-half
    const int gid = lane >> 2, tig = lane & 3;

    float* sbht = (float*)(sm + OFF_BHT);
    float* sbrl = (float*)(sm + OFF_BREL);
    float* sEp  = (float*)(sm + OFF_EP)  + s * 128;
    int*   sIds = (int*)  (sm + OFF_IDS) + s * 304;   // two buffers of 152
    float* sXf  = (float*)(sm + OFF_XF   + s * XF_TILE);
    float* sRf  = (float*)(sm + OFF_RELF + s * RF_TILE);

    // ---- zero weights + staging (pads must be 0 and stay 0) ----
    for (int i = tid; i < ZERO_BYTES / 16; i += THREADS)
        ((uint4*)sm)[i] = make_uint4(0, 0, 0, 0);
    __syncthreads();

    // ---- weights -> fp16 smem ----
    {
        const float4* g = (const float4*)Wht;              // [100][200] -> 5000 f4
        for (int i = tid; i < 5000; i += THREADS) {
            int d = i / 50, c4 = i % 50;
            float4 v = __ldg(&g[i]);
            uint2 hv; hv.x = f2h2(v.x, v.y); hv.y = f2h2(v.z, v.w);
            *(uint2*)(sm + OFF_WHT + (d * SWH + c4 * 4) * 2) = hv;
        }
        const float4* gr = (const float4*)Wrel;            // [100][100] -> 2500 f4
        for (int i = tid; i < 2500; i += THREADS) {
            int d = i / 25, c4 = i % 25;
            float4 v = __ldg(&gr[i]);
            uint2 hv; hv.x = f2h2(v.x, v.y); hv.y = f2h2(v.z, v.w);
            *(uint2*)(sm + OFF_WREL + (d * SWR + c4 * 4) * 2) = hv;
        }
        if (tid < 112) {
            sbht[tid] = (tid < D_) ? bht[tid]  : 0.f;
            sbrl[tid] = (tid < D_) ? brel[tid] : 0.f;
        }
    }
    const int is64 = ((idsw[1] | idsw[3] | idsw[5] | idsw[7]) == 0) ? 1 : 0;
    __syncthreads();   // after this the two halves decouple

    const int mt = w & 3, nh = (w >> 2) & 1;
    const int arow = mt * 16 + gid;
    const int row0 = (arow     < K_) ? arow     : (K_ - 1);
    const int row1 = (arow + 8 < K_) ? arow + 8 : (K_ - 1);
    const bool skipA1 = (mt == 3);        // rows 56..63 all clamp & discard
    const __half* pWH = (const __half*)(sm + OFF_WHT);
    const __half* pWR = (const __half*)(sm + OFF_WREL);
    const uint32_t dXb = sb + OFF_XF   + s * XF_TILE + lane * 16;
    const uint32_t dRb = sb + OFF_RELF + s * RF_TILE + lane * 16;

    const int hs = blockIdx.x * 2 + s;
    const int NH = gridDim.x * 2;

    // wsum role (constant per thread); clamp inactive threads to a safe column
    const int wpart = (ht < 100) ? 0 : 2;
    const int wcol  = (ht < 100) ? ht : ((ht < 200) ? ht - 100 : 0);

    // ---- prologue: ids + gather for the first tile (separate commit groups) ----
    if (ht < 150) {
        const long long e = (long long)hs * 150 + ht;
        sIds[ht] = (int)(is64 ? idsw[2 * e] : idsw[e]);
    }
    BARH(s);
    if (lane < 25) {
        for (int task = wh; task < 50; task += 8) {
            const int id = sIds[task * 3 + 1];
            cp_async16(dRb + task * SRF * 4,
                       (const char*)emb + (long long)id * 400 + lane * 16);
        }
    }
    CP_COMMIT();   // group: REL
    if (lane < 25) {
        for (int task = wh; task < 100; task += 8) {
            const int k = task >> 1, h = task & 1;
            const int id = sIds[k * 3 + (h ? 2 : 0)];
            cp_async16(dXb + (k * SXF + h * 100) * 4,
                       (const char*)emb + (long long)id * 400 + lane * 16);
        }
    }
    CP_COMMIT();   // group: X

    int pp = 0;
    for (int tile = hs; tile < NTILES; tile += NH) {
        const bool has_next = (tile + NH) < NTILES;
        int* curIds = sIds + pp * 152;
        int* nxtIds = sIds + (pp ^ 1) * 152;

        // next-tile ids: issue LDG BEFORE the wait so its latency overlaps it
        int rid = 0;
        const bool pre = has_next && (ht < 150);
        if (pre) {
            const long long e = (long long)(tile + NH) * 150 + ht;
            rid = (int)(is64 ? idsw[2 * e] : idsw[e]);
        }

        CP_WAIT1();   // REL landed (X may still be in flight)
        BARH(s);      // all warps' REL visible; prev-phase smem reads ordered

        float acc1[7][4], acc2[7][4];
#pragma unroll
        for (int nt = 0; nt < 7; nt++)
#pragma unroll
            for (int j = 0; j < 4; j++) { acc1[nt][j] = 0.f; acc2[nt][j] = 0.f; }

        {   // GEMM2: D2 = REL[64x112] @ Wrel[112x112]^T
            const float* pA0 = sRf + row0 * SRF;
            const float* pA1 = sRf + row1 * SRF;
#pragma unroll
            for (int ks = 0; ks < 7; ks++) {
                const int k0 = ks * 16 + tig * 2;
                float2 f0 = *(const float2*)(pA0 + k0);
                float2 f2 = *(const float2*)(pA0 + k0 + 8);
                float2 f1 = skipA1 ? f0 : *(const float2*)(pA1 + k0);
                float2 f3 = skipA1 ? f2 : *(const float2*)(pA1 + k0 + 8);
                uint32_t a0 = f2h2(f0.x, f0.y), a1 = f2h2(f1.x, f1.y);
                uint32_t a2 = f2h2(f2.x, f2.y), a3 = f2h2(f3.x, f3.y);
#pragma unroll
                for (int nt = 0; nt < 7; nt++) {
                    const int brow = nh * 56 + nt * 8 + gid;
                    uint32_t b0 = *(const uint32_t*)(pWR + brow * SWR + k0);
                    uint32_t b1 = *(const uint32_t*)(pWR + brow * SWR + k0 + 8);
                    mma16816(acc2[nt][0], acc2[nt][1], acc2[nt][2], acc2[nt][3],
                             a0, a1, a2, a3, b0, b1);
                }
            }
        }
        if (pre) nxtIds[ht] = rid;
        CP_WAIT0();   // X landed
        BARH(s);      // all warps: GEMM2 done with sRf; X + next ids visible

        // overlap: next tile's REL gather streams in under GEMM1 + epilogue
        if (has_next && lane < 25) {
            for (int task = wh; task < 50; task += 8) {
                const int id = nxtIds[task * 3 + 1];
                cp_async16(dRb + task * SRF * 4,
                           (const char*)emb + (long long)id * 400 + lane * 16);
            }
        }
        CP_COMMIT();   // group: REL

        {   // GEMM1: D1 = X[64x208] @ Wht[112x208]^T
            const float* pA0 = sXf + row0 * SXF;
            const float* pA1 = sXf + row1 * SXF;
#pragma unroll
            for (int ks = 0; ks < 13; ks++) {
                const int k0 = ks * 16 + tig * 2;
                float2 f0 = *(const float2*)(pA0 + k0);
                float2 f2 = *(const float2*)(pA0 + k0 + 8);
                float2 f1 = skipA1 ? f0 : *(const float2*)(pA1 + k0);
                float2 f3 = skipA1 ? f2 : *(const float2*)(pA1 + k0 + 8);
                uint32_t a0 = f2h2(f0.x, f0.y), a1 = f2h2(f1.x, f1.y);
                uint32_t a2 = f2h2(f2.x, f2.y), a3 = f2h2(f3.x, f3.y);
#pragma unroll
                for (int nt = 0; nt < 7; nt++) {
                    const int brow = nh * 56 + nt * 8 + gid;
                    uint32_t b0 = *(const uint32_t*)(pWH + brow * SWH + k0);
                    uint32_t b1 = *(const uint32_t*)(pWH + brow * SWH + k0 + 8);
                    mma16816(acc1[nt][0], acc1[nt][1], acc1[nt][2], acc1[nt][3],
                             a0, a1, a2, a3, b0, b1);
                }
            }
        }

        // ---- fused epilogue: e partials (pad cols contribute 0) ----
        {
            float e0 = 0.f, e1 = 0.f;
#pragma unroll
            for (int nt = 0; nt < 7; nt++) {
                const int c0 = nh * 56 + nt * 8 + tig * 2;
                const float bh0 = sbht[c0], bh1 = sbht[c0 + 1];
                const float br0 = sbrl[c0], br1 = sbrl[c0 + 1];
                e0 += tanh_approx(acc1[nt][0] + bh0) * (acc2[nt][0] + br0)
                    + tanh_approx(acc1[nt][1] + bh1) * (acc2[nt][1] + br1);
                e1 += tanh_approx(acc1[nt][2] + bh0) * (acc2[nt][2] + br0)
                    + tanh_approx(acc1[nt][3] + bh1) * (acc2[nt][3] + br1);
            }
            e0 += __shfl_xor_sync(0xffffffffu, e0, 1);
            e0 += __shfl_xor_sync(0xffffffffu, e0, 2);
            e1 += __shfl_xor_sync(0xffffffffu, e1, 1);
            e1 += __shfl_xor_sync(0xffffffffu, e1, 2);
            if (tig == 0) {
                sEp[nh * 64 + arow]     = e0;
                sEp[nh * 64 + arow + 8] = e1;
            }
        }
        BARH(s);   // sXf free for overwrite; sEp ready

        // overlap: next tile's X gather streams in under softmax + wsum
        if (has_next && lane < 25) {
            for (int task = wh; task < 100; task += 8) {
                const int k = task >> 1, h = task & 1;
                const int id = nxtIds[k * 3 + (h ? 2 : 0)];
                cp_async16(dXb + (k * SXF + h * 100) * 4,
                           (const char*)emb + (long long)id * 400 + lane * 16);
            }
        }
        CP_COMMIT();   // group: X

        // ---- wsum loads batch 1 (MLP=25) issued BEFORE softmax to hide L2 latency ----
        const float* ebase = emb + wcol;
        float v1[25];
        const bool dow = (wh < 7);
        if (dow) {
#pragma unroll
            for (int j = 0; j < 25; j++) {
                const int id = curIds[j * 3 + wpart];
                v1[j] = __ldg(ebase + (long long)id * D_);
            }
        }

        // ---- softmax (redundant per-warp, registers only) ----
        float al0, al1;
        {
            float v0 = (lane < K_) ? (sEp[lane] + sEp[64 + lane]) : -1e30f;
            float vv1 = (lane + 32 < K_) ? (sEp[lane + 32] + sEp[64 + lane + 32]) : -1e30f;
            float m = fmaxf(v0, vv1);
#pragma unroll
            for (int off = 16; off > 0; off >>= 1)
                m = fmaxf(m, __shfl_xor_sync(0xffffffffu, m, off));
            float x0 = (lane < K_) ? __expf(v0 - m) : 0.f;
            float x1 = (lane + 32 < K_) ? __expf(vv1 - m) : 0.f;
            float su = x0 + x1;
#pragma unroll
            for (int off = 16; off > 0; off >>= 1)
                su += __shfl_xor_sync(0xffffffffu, su, off);
            const float inv = __fdividef(1.f, su);
            al0 = x0 * inv;        // alpha[lane]
            al1 = x1 * inv;        // alpha[lane+32]
        }

        // ---- wsum: issue batch 2, consume batch 1, consume batch 2 ----
        if (dow) {
            float v2[25];
#pragma unroll
            for (int j = 0; j < 25; j++) {
                const int id = curIds[(25 + j) * 3 + wpart];
                v2[j] = __ldg(ebase + (long long)id * D_);
            }
            float acc = 0.f;
#pragma unroll
            for (int j = 0; j < 25; j++) {
                const float al = __shfl_sync(0xffffffffu, al0, j);
                acc += al * v1[j];
            }
#pragma unroll
            for (int j = 0; j < 25; j++) {
                const int k = 25 + j;
                const float al = (k < 32) ? __shfl_sync(0xffffffffu, al0, k)
                                          : __shfl_sync(0xffffffffu, al1, k - 32);
                acc += al * v2[j];
            }
            if (ht < 200) out[(long long)tile * 200 + ht] = acc;
        }
        // no trailing barrier: next iteration's head BARH orders
        // sEp reads vs next epilogue writes and curIds reads vs next id stores.
        pp ^= 1;
    }
}

extern "C" void kernel_launch(void* const* d_in, const int* in_sizes, int n_in,
                              void* d_out, int out_size) {
    const unsigned int* ids = nullptr;
    const float *emb = nullptr, *Wht = nullptr, *Wrel = nullptr;
    const float *bht = nullptr, *brel = nullptr;

    for (int i = 0; i < n_in; i++) {
        const int sz = in_sizes[i];
        if      (sz == B_ * T_ * K_ * 3) ids  = (const unsigned int*)d_in[i];
        else if (sz == 500000 * D_)      emb  = (const float*)d_in[i];
        else if (sz == D_ * 2 * D_)      Wht  = (const float*)d_in[i];
        else if (sz == D_ * D_)          Wrel = (const float*)d_in[i];
        else if (sz == D_) {
            if (!bht) bht = (const float*)d_in[i];
            else      brel = (const float*)d_in[i];
        }
    }

    int dev = 0;
    cudaGetDevice(&dev);
    int sms = 148;
    cudaDeviceGetAttribute(&sms, cudaDevAttrMultiProcessorCount, dev);
    if (sms <= 0) sms = 148;

    cudaFuncSetAttribute(outer_encoder_mma,
                         cudaFuncAttributeMaxDynamicSharedMemorySize, SMEM_BYTES);
    outer_encoder_mma<<<sms, THREADS, SMEM_BYTES>>>(
        ids, emb, Wht, bht, Wrel, brel, (float*)d_out);
}